// round 2
// baseline (speedup 1.0000x reference)
#include <cuda_runtime.h>
#include <math.h>

#define NMATS 200
#define BATCH 64
#define DIM 64
#define TOTAL (NMATS * BATCH)      // 12800
#define MATELEMS (DIM * DIM)       // 4096
#define LDU 65                     // padded column stride (bank-conflict mitigation)
#define NSWEEPS 9

// Scratch: per-matrix logm results (210 MB) + per-batch mean-of-logs (1 MB).
__device__ float g_logm[(size_t)TOTAL * MATELEMS];
__device__ float g_mean[BATCH * MATELEMS];

// ---------------------------------------------------------------------------
// Stage 1: one-sided (Hestenes) Jacobi per matrix; 1 warp per matrix.
// Converged U = Q*Lambda (X SPD), so logm(X) = sum_j g_j u_j u_j^T with
// g_j = 0.5*log(||u_j||^2)/||u_j||^2.
// ---------------------------------------------------------------------------
__global__ __launch_bounds__(32) void jacobi_log_kernel(const float* __restrict__ X)
{
    __shared__ float U[DIM * LDU];
    __shared__ float gcoef[DIM];
    const int t = threadIdx.x;                 // 0..31 : pair index
    const size_t mat = blockIdx.x;             // 0..12799  (= i*BATCH + b)
    const float* Xm = X + mat * (size_t)MATELEMS;

    // Load. X is symmetric, so column c == row c; coalesced global reads,
    // conflict-free smem stores (consecutive r).
    for (int idx = t; idx < MATELEMS; idx += 32) {
        int c = idx >> 6, r = idx & 63;
        U[c * LDU + r] = Xm[idx];
    }
    __syncwarp();

    for (int sweep = 0; sweep < NSWEEPS; ++sweep) {
        for (int r = 0; r < 63; ++r) {
            // Round-robin tournament: element 63 fixed, others rotate.
            int p, q;
            if (t == 0) { p = 63; q = r; }
            else {
                p = r + t;      if (p >= 63) p -= 63;
                q = r - t;      if (q < 0)   q += 63;
            }
            float* up = &U[p * LDU];
            float* uq = &U[q * LDU];

            // Gram entries of the column pair (2-way split chains for ILP).
            float s00 = 0.f, s01 = 0.f, s11 = 0.f;
            float u00 = 0.f, u01 = 0.f, u11 = 0.f;
            #pragma unroll 8
            for (int i = 0; i < DIM; i += 2) {
                float x0 = up[i],     y0 = uq[i];
                float x1 = up[i + 1], y1 = uq[i + 1];
                s00 = fmaf(x0, x0, s00); s01 = fmaf(x0, y0, s01); s11 = fmaf(y0, y0, s11);
                u00 = fmaf(x1, x1, u00); u01 = fmaf(x1, y1, u01); u11 = fmaf(y1, y1, u11);
            }
            float a00 = s00 + u00, a01 = s01 + u01, a11 = s11 + u11;

            float thr = 1e-7f * sqrtf(a00 * a11);
            bool act = fabsf(a01) > thr;
            float c = 1.f, s = 0.f;
            if (act) {
                // Zero the Gram off-diagonal of the rotated pair.
                // t solves t^2 - 2*tau*t - 1 = 0, tau = (a00-a11)/(2*a01); take small root.
                float tau = (a00 - a11) / (2.f * a01);
                float tt  = -copysignf(1.f, tau) / (fabsf(tau) + sqrtf(1.f + tau * tau));
                c = rsqrtf(1.f + tt * tt);
                s = tt * c;
            }
            // Collective skip once (nearly) converged.
            if (__any_sync(0xffffffffu, act)) {
                #pragma unroll 8
                for (int i = 0; i < DIM; ++i) {
                    float x = up[i], y = uq[i];
                    up[i] = fmaf(c, x, -s * y);   // u_p' = c*u_p - s*u_q
                    uq[i] = fmaf(s, x,  c * y);   // u_q' = s*u_p + c*u_q
                }
            }
            __syncwarp();
        }
    }

    // Column norms -> spectral coefficients g_j = log(lambda_j)/lambda_j^2.
    for (int h = 0; h < 2; ++h) {
        int j = t + h * 32;
        const float* uj = &U[j * LDU];
        float n0 = 0.f, n1 = 0.f;
        #pragma unroll 8
        for (int i = 0; i < DIM; i += 2) {
            n0 = fmaf(uj[i],     uj[i],     n0);
            n1 = fmaf(uj[i + 1], uj[i + 1], n1);
        }
        float nn = n0 + n1;                       // lambda_j^2
        gcoef[j] = 0.5f * logf(nn) / nn;
    }
    __syncwarp();

    // Reconstruct logm = sum_j g_j u_j u_j^T.
    // Thread t computes rows t and t+32; store as columns (symmetric) so
    // global writes are coalesced.
    float* outm = g_logm + mat * (size_t)MATELEMS;
    for (int mi = 0; mi < 2; ++mi) {
        int m = t + mi * 32;
        for (int h = 0; h < 2; ++h) {
            float acc[32];
            #pragma unroll
            for (int n = 0; n < 32; ++n) acc[n] = 0.f;
            for (int j = 0; j < DIM; ++j) {
                float a = gcoef[j] * U[j * LDU + m];
                const float* uj = &U[j * LDU + h * 32];
                #pragma unroll
                for (int n = 0; n < 32; ++n) acc[n] = fmaf(a, uj[n], acc[n]);
            }
            #pragma unroll
            for (int n = 0; n < 32; ++n)
                outm[(size_t)(h * 32 + n) * DIM + m] = acc[n];
        }
    }
}

// ---------------------------------------------------------------------------
// Stage 2: mean over N. offset(i,b,e) = i*(BATCH*MATELEMS) + (b*MATELEMS+e).
// ---------------------------------------------------------------------------
__global__ void mean_kernel()
{
    int idx = blockIdx.x * blockDim.x + threadIdx.x;   // = b*MATELEMS + e
    if (idx >= BATCH * MATELEMS) return;
    const float* p = g_logm + idx;
    float s = 0.f;
    #pragma unroll 4
    for (int i = 0; i < NMATS; ++i)
        s += p[(size_t)i * (BATCH * MATELEMS)];
    g_mean[idx] = s * (1.f / NMATS);
}

// ---------------------------------------------------------------------------
// Stage 3: expm via scaling-and-squaring Taylor. ||M|| <= ~2.31, E = M/16,
// degree-8 Horner, then 4 squarings. One block (256 threads) per batch entry.
// Only TWO smem buffers (E, P): matmul results live in registers, written
// back into P after a barrier (each output element owned by one thread).
// ---------------------------------------------------------------------------
__device__ __forceinline__ void mm_acc(float* __restrict__ acc,
                                       const float* __restrict__ A,
                                       const float* __restrict__ Bm,
                                       int m, int nb)
{
    #pragma unroll
    for (int n = 0; n < 16; ++n) acc[n] = 0.f;
    for (int j = 0; j < DIM; ++j) {
        float a = A[m * LDU + j];
        const float* brow = &Bm[j * LDU + nb];
        #pragma unroll
        for (int n = 0; n < 16; ++n) acc[n] = fmaf(a, brow[n], acc[n]);
    }
}

__global__ __launch_bounds__(256) void expm_kernel(float* __restrict__ out)
{
    __shared__ float E[DIM * LDU];
    __shared__ float P[DIM * LDU];
    const int b = blockIdx.x;
    const int tid = threadIdx.x;
    const int m  = tid >> 2;          // output row
    const int nb = (tid & 3) << 4;    // output col base (16-wide strip)

    // E = mean/16 ; P = I + E/8
    for (int idx = tid; idx < MATELEMS; idx += 256) {
        int r = idx >> 6, c = idx & 63;
        float e = g_mean[b * MATELEMS + idx] * (1.f / 16.f);
        E[r * LDU + c] = e;
        P[r * LDU + c] = e * 0.125f + (r == c ? 1.f : 0.f);
    }
    __syncthreads();

    // Horner: P <- I + (E*P)/k, k = 7..1  => P = sum_{k<=8} E^k/k!
    for (int k = 7; k >= 1; --k) {
        float acc[16];
        mm_acc(acc, E, P, m, nb);
        __syncthreads();              // all reads of P done
        float inv = 1.f / (float)k;
        #pragma unroll
        for (int n = 0; n < 16; ++n)
            P[m * LDU + nb + n] = acc[n] * inv + ((m == nb + n) ? 1.f : 0.f);
        __syncthreads();
    }

    // 4 squarings: exp(M) = (exp(M/16))^(16)
    for (int sq = 0; sq < 4; ++sq) {
        float acc[16];
        mm_acc(acc, P, P, m, nb);
        __syncthreads();
        #pragma unroll
        for (int n = 0; n < 16; ++n)
            P[m * LDU + nb + n] = acc[n];
        __syncthreads();
    }

    for (int idx = tid; idx < MATELEMS; idx += 256) {
        int r = idx >> 6, c = idx & 63;
        out[(size_t)b * MATELEMS + idx] = P[r * LDU + c];
    }
}

// ---------------------------------------------------------------------------
extern "C" void kernel_launch(void* const* d_in, const int* in_sizes, int n_in,
                              void* d_out, int out_size)
{
    (void)in_sizes; (void)n_in; (void)out_size;
    const float* X = (const float*)d_in[0];
    float* out = (float*)d_out;

    jacobi_log_kernel<<<TOTAL, 32>>>(X);
    mean_kernel<<<(BATCH * MATELEMS + 255) / 256, 256>>>();
    expm_kernel<<<BATCH, 256>>>(out);
}

// round 3
// speedup vs baseline: 2.0504x; 2.0504x over previous
#include <cuda_runtime.h>
#include <math.h>

#define NMATS 200
#define BATCH 64
#define DIM 64
#define TOTAL (NMATS * BATCH)      // 12800
#define MATELEMS (DIM * DIM)       // 4096
#define LDU 65                     // padded column stride
#define NSWEEPS 8

// Scratch: per-matrix logm results (210 MB) + per-batch mean-of-logs (1 MB).
__device__ float g_logm[(size_t)TOTAL * MATELEMS];
__device__ float g_mean[BATCH * MATELEMS];

// ---------------------------------------------------------------------------
// Stage 1: register-resident one-sided (Hestenes) Jacobi, Brent-Luk ordering.
// 1 warp per matrix; thread t owns two full columns (a, b) in registers.
// Converged U = Q*Lambda (X SPD)  =>  logm(X) = sum_j g_j u_j u_j^T,
// g_j = 0.5*log(||u_j||^2)/||u_j||^2.
// ---------------------------------------------------------------------------
__global__ __launch_bounds__(32) void jacobi_log_kernel(const float* __restrict__ X)
{
    __shared__ float U[DIM * LDU];      // staging (load) + reconstruction
    __shared__ float gcoef[DIM];
    const int t = threadIdx.x;
    const size_t mat = blockIdx.x;
    const float* Xm = X + mat * (size_t)MATELEMS;

    // Coalesced global load into smem (X symmetric: row c == column c).
    for (int idx = t; idx < MATELEMS; idx += 32) {
        int c = idx >> 6, r = idx & 63;
        U[c * LDU + r] = Xm[idx];
    }
    __syncwarp();

    // Pull two columns into registers: a = col 2t, b = col 2t+1.
    float a[DIM], b[DIM];
    #pragma unroll
    for (int i = 0; i < DIM; ++i) a[i] = U[(2 * t) * LDU + i];
    #pragma unroll
    for (int i = 0; i < DIM; ++i) b[i] = U[(2 * t + 1) * LDU + i];

    const bool is0 = (t == 0), is31 = (t == 31);

    for (int sweep = 0; sweep < NSWEEPS; ++sweep) {
        bool sweep_active = false;
        for (int r = 0; r < 63; ++r) {
            // Gram of the owned pair — pure register FMAs, 3 independent chains.
            float s00 = 0.f, s01 = 0.f, s11 = 0.f;
            #pragma unroll
            for (int i = 0; i < DIM; ++i) {
                float x = a[i], y = b[i];
                s00 = fmaf(x, x, s00);
                s01 = fmaf(x, y, s01);
                s11 = fmaf(y, y, s11);
            }

            float thr = 1e-7f * sqrtf(s00 * s11);
            bool act = fabsf(s01) > thr;
            if (__any_sync(0xffffffffu, act)) {
                sweep_active = true;
                float c = 1.f, s = 0.f;
                if (act) {
                    float tau = (s00 - s11) / (2.f * s01);
                    float tt  = -copysignf(1.f, tau) / (fabsf(tau) + sqrtf(1.f + tau * tau));
                    c = rsqrtf(1.f + tt * tt);
                    s = tt * c;
                }
                #pragma unroll
                for (int i = 0; i < DIM; ++i) {
                    float x = a[i], y = b[i];
                    a[i] = fmaf(c, x, -s * y);
                    b[i] = fmaf(s, x,  c * y);
                }
            }

            // Brent-Luk tournament rotation (circle method), 2 shfl per element:
            //   new_top[0]=top[0]; new_top[1]=bot[0]; new_top[j]=top[j-1]
            //   new_bot[31]=top[31]; new_bot[j]=bot[j+1]
            #pragma unroll
            for (int i = 0; i < DIM; ++i) {
                float send = is0 ? b[i] : a[i];
                float nt = __shfl_up_sync(0xffffffffu, send, 1);
                float nb = __shfl_down_sync(0xffffffffu, b[i], 1);
                float na = is0 ? a[i] : nt;
                nb = is31 ? a[i] : nb;
                a[i] = na;
                b[i] = nb;
            }
        }
        if (!sweep_active) break;
    }

    // Write converged columns back to smem; compute spectral coefficients.
    #pragma unroll
    for (int i = 0; i < DIM; ++i) U[(2 * t) * LDU + i] = a[i];
    #pragma unroll
    for (int i = 0; i < DIM; ++i) U[(2 * t + 1) * LDU + i] = b[i];

    {
        float na0 = 0.f, na1 = 0.f, nb0 = 0.f, nb1 = 0.f;
        #pragma unroll
        for (int i = 0; i < DIM; i += 2) {
            na0 = fmaf(a[i], a[i], na0);     na1 = fmaf(a[i + 1], a[i + 1], na1);
            nb0 = fmaf(b[i], b[i], nb0);     nb1 = fmaf(b[i + 1], b[i + 1], nb1);
        }
        float nna = na0 + na1;               // lambda^2 of col a
        float nnb = nb0 + nb1;
        gcoef[2 * t]     = 0.5f * logf(nna) / nna;
        gcoef[2 * t + 1] = 0.5f * logf(nnb) / nnb;
    }
    __syncwarp();

    // Reconstruct logm = sum_j g_j u_j u_j^T. Thread t computes rows t, t+32;
    // stores transposed (symmetric) so global writes coalesce over lanes.
    float* outm = g_logm + mat * (size_t)MATELEMS;
    for (int mi = 0; mi < 2; ++mi) {
        int m = t + mi * 32;
        for (int h = 0; h < 2; ++h) {
            float acc[32];
            #pragma unroll
            for (int n = 0; n < 32; ++n) acc[n] = 0.f;
            for (int j = 0; j < DIM; ++j) {
                float aj = gcoef[j] * U[j * LDU + m];
                const float* uj = &U[j * LDU + h * 32];
                #pragma unroll
                for (int n = 0; n < 32; ++n) acc[n] = fmaf(aj, uj[n], acc[n]);
            }
            #pragma unroll
            for (int n = 0; n < 32; ++n)
                outm[(size_t)(h * 32 + n) * DIM + m] = acc[n];
        }
    }
}

// ---------------------------------------------------------------------------
// Stage 2: mean over N.
// ---------------------------------------------------------------------------
__global__ void mean_kernel()
{
    int idx = blockIdx.x * blockDim.x + threadIdx.x;   // = b*MATELEMS + e
    if (idx >= BATCH * MATELEMS) return;
    const float* p = g_logm + idx;
    float s = 0.f;
    #pragma unroll 4
    for (int i = 0; i < NMATS; ++i)
        s += p[(size_t)i * (BATCH * MATELEMS)];
    g_mean[idx] = s * (1.f / NMATS);
}

// ---------------------------------------------------------------------------
// Stage 3: expm via scaling-and-squaring Taylor. E = mean/16, degree-8
// Horner, 4 squarings. One 256-thread block per batch entry; two smem
// buffers, matmul results held in registers across the barrier.
// ---------------------------------------------------------------------------
__device__ __forceinline__ void mm_acc(float* __restrict__ acc,
                                       const float* __restrict__ A,
                                       const float* __restrict__ Bm,
                                       int m, int nb)
{
    #pragma unroll
    for (int n = 0; n < 16; ++n) acc[n] = 0.f;
    for (int j = 0; j < DIM; ++j) {
        float av = A[m * LDU + j];
        const float* brow = &Bm[j * LDU + nb];
        #pragma unroll
        for (int n = 0; n < 16; ++n) acc[n] = fmaf(av, brow[n], acc[n]);
    }
}

__global__ __launch_bounds__(256) void expm_kernel(float* __restrict__ out)
{
    __shared__ float E[DIM * LDU];
    __shared__ float P[DIM * LDU];
    const int b = blockIdx.x;
    const int tid = threadIdx.x;
    const int m  = tid >> 2;
    const int nb = (tid & 3) << 4;

    for (int idx = tid; idx < MATELEMS; idx += 256) {
        int r = idx >> 6, c = idx & 63;
        float e = g_mean[b * MATELEMS + idx] * (1.f / 16.f);
        E[r * LDU + c] = e;
        P[r * LDU + c] = e * 0.125f + (r == c ? 1.f : 0.f);
    }
    __syncthreads();

    for (int k = 7; k >= 1; --k) {
        float acc[16];
        mm_acc(acc, E, P, m, nb);
        __syncthreads();
        float inv = 1.f / (float)k;
        #pragma unroll
        for (int n = 0; n < 16; ++n)
            P[m * LDU + nb + n] = acc[n] * inv + ((m == nb + n) ? 1.f : 0.f);
        __syncthreads();
    }

    for (int sq = 0; sq < 4; ++sq) {
        float acc[16];
        mm_acc(acc, P, P, m, nb);
        __syncthreads();
        #pragma unroll
        for (int n = 0; n < 16; ++n)
            P[m * LDU + nb + n] = acc[n];
        __syncthreads();
    }

    for (int idx = tid; idx < MATELEMS; idx += 256) {
        int r = idx >> 6, c = idx & 63;
        out[(size_t)b * MATELEMS + idx] = P[r * LDU + c];
    }
}

// ---------------------------------------------------------------------------
extern "C" void kernel_launch(void* const* d_in, const int* in_sizes, int n_in,
                              void* d_out, int out_size)
{
    (void)in_sizes; (void)n_in; (void)out_size;
    const float* X = (const float*)d_in[0];
    float* out = (float*)d_out;

    jacobi_log_kernel<<<TOTAL, 32>>>(X);
    mean_kernel<<<(BATCH * MATELEMS + 255) / 256, 256>>>();
    expm_kernel<<<BATCH, 256>>>(out);
}

// round 5
// speedup vs baseline: 2.9175x; 1.4229x over previous
#include <cuda_runtime.h>
#include <math.h>

#define NMATS 200
#define BATCH 64
#define DIM 64
#define TOTAL (NMATS * BATCH)      // 12800
#define MATELEMS (DIM * DIM)       // 4096
#define LDU 65
#define NSWEEPS 8
#define FULLMASK 0xffffffffu

__device__ float g_logm[(size_t)TOTAL * MATELEMS];
__device__ float g_mean[BATCH * MATELEMS];

// ---------------------------------------------------------------------------
// Stage 1: register-resident one-sided Jacobi (Brent-Luk circle ordering)
// with incremental norm tracking and deferred-cosine (scaled) rotations.
// 1 warp per matrix; thread t owns two columns in registers plus traveling
// scalars (norm, scale) that follow the columns through the tournament.
// ---------------------------------------------------------------------------
__global__ __launch_bounds__(32) void jacobi_log_kernel(const float* __restrict__ X)
{
    __shared__ float U[DIM * LDU];
    __shared__ float gcoef[DIM];
    const int t = threadIdx.x;
    const size_t mat = blockIdx.x;
    const float* Xm = X + mat * (size_t)MATELEMS;

    // Coalesced load (X symmetric: row c == column c).
    for (int idx = t; idx < MATELEMS; idx += 32) {
        int c = idx >> 6, r = idx & 63;
        U[c * LDU + r] = Xm[idx];
    }
    __syncwarp();

    float a[DIM], b[DIM];
    #pragma unroll
    for (int i = 0; i < DIM; ++i) a[i] = U[(2 * t) * LDU + i];
    #pragma unroll
    for (int i = 0; i < DIM; ++i) b[i] = U[(2 * t + 1) * LDU + i];

    // Initial column norms (actual), traveling scales = 1.
    float na, nb;
    {
        float p0 = 0.f, p1 = 0.f, q0 = 0.f, q1 = 0.f;
        #pragma unroll
        for (int i = 0; i < DIM; i += 2) {
            p0 = fmaf(a[i], a[i], p0);     p1 = fmaf(a[i+1], a[i+1], p1);
            q0 = fmaf(b[i], b[i], q0);     q1 = fmaf(b[i+1], b[i+1], q1);
        }
        na = p0 + p1; nb = q0 + q1;
    }
    float sa = 1.f, sb = 1.f;

    const bool is0 = (t == 0), is31 = (t == 31);

    for (int sweep = 0; sweep < NSWEEPS; ++sweep) {
        bool sweep_active = false;
        for (int r = 0; r < 63; ++r) {
            // Cross dot of stored (scaled) columns, 4 chains for ILP.
            float d0 = 0.f, d1 = 0.f, d2 = 0.f, d3 = 0.f;
            #pragma unroll
            for (int i = 0; i < DIM; i += 4) {
                d0 = fmaf(a[i],     b[i],     d0);
                d1 = fmaf(a[i + 1], b[i + 1], d1);
                d2 = fmaf(a[i + 2], b[i + 2], d2);
                d3 = fmaf(a[i + 3], b[i + 3], d3);
            }
            float s01 = (d0 + d1) + (d2 + d3);
            float a01 = s01 * sa * sb;                 // actual off-diagonal

            float thr = 1e-7f * sqrtf(na * nb);
            bool act = fabsf(a01) > thr;

            float t1 = 0.f, t2 = 0.f;
            if (act) {
                float tau = (na - nb) / (2.f * a01);
                float tt  = -copysignf(1.f, tau) / (fabsf(tau) + sqrtf(1.f + tau * tau));
                float c   = rsqrtf(1.f + tt * tt);
                float rr  = __fdividef(sb, sa);        // sb/sa
                t1 = tt * rr;                          // applied to stored y
                t2 = __fdividef(tt, rr);               // applied to stored x
                na = fmaf(-tt, a01, na);               // a00' = a00 - t*a01
                nb = fmaf( tt, a01, nb);               // a11' = a11 + t*a01
                sa *= c; sb *= c;                      // deferred cosine
            }

            bool anyact = __any_sync(FULLMASK, act);
            sweep_active |= anyact;

            if (anyact) {
                // Fused rotate + tournament exchange.
                #pragma unroll
                for (int i = 0; i < DIM; ++i) {
                    float x = a[i], y = b[i];
                    float xn = fmaf(-t1, y, x);
                    float yn = fmaf( t2, x, y);
                    float send = is0 ? yn : xn;
                    float up = __shfl_up_sync(FULLMASK, send, 1);
                    float dn = __shfl_down_sync(FULLMASK, yn, 1);
                    a[i] = is0 ? xn : up;
                    b[i] = is31 ? xn : dn;
                }
            } else {
                #pragma unroll
                for (int i = 0; i < DIM; ++i) {
                    float xn = a[i], yn = b[i];
                    float send = is0 ? yn : xn;
                    float up = __shfl_up_sync(FULLMASK, send, 1);
                    float dn = __shfl_down_sync(FULLMASK, yn, 1);
                    a[i] = is0 ? xn : up;
                    b[i] = is31 ? xn : dn;
                }
            }

            // Traveling scalars follow the same routing.
            {
                float sn = is0 ? nb : na;
                float un = __shfl_up_sync(FULLMASK, sn, 1);
                float dnn = __shfl_down_sync(FULLMASK, nb, 1);
                float na2 = is0 ? na : un;
                float nb2 = is31 ? na : dnn;

                float ss = is0 ? sb : sa;
                float us = __shfl_up_sync(FULLMASK, ss, 1);
                float dss = __shfl_down_sync(FULLMASK, sb, 1);
                float sa2 = is0 ? sa : us;
                float sb2 = is31 ? sa : dss;

                na = na2; nb = nb2; sa = sa2; sb = sb2;
            }
        }

        // Renormalize stored columns to actual values once per sweep.
        #pragma unroll
        for (int i = 0; i < DIM; ++i) { a[i] *= sa; b[i] *= sb; }
        sa = 1.f; sb = 1.f;

        if (!sweep_active) break;
    }

    // Exact final norms -> spectral coefficients; stash columns in smem.
    #pragma unroll
    for (int i = 0; i < DIM; ++i) U[(2 * t) * LDU + i] = a[i];
    #pragma unroll
    for (int i = 0; i < DIM; ++i) U[(2 * t + 1) * LDU + i] = b[i];
    {
        float p0 = 0.f, p1 = 0.f, q0 = 0.f, q1 = 0.f;
        #pragma unroll
        for (int i = 0; i < DIM; i += 2) {
            p0 = fmaf(a[i], a[i], p0);     p1 = fmaf(a[i+1], a[i+1], p1);
            q0 = fmaf(b[i], b[i], q0);     q1 = fmaf(b[i+1], b[i+1], q1);
        }
        float nna = p0 + p1, nnb = q0 + q1;        // lambda^2
        gcoef[2 * t]     = 0.5f * logf(nna) / nna;
        gcoef[2 * t + 1] = 0.5f * logf(nnb) / nnb;
    }
    __syncwarp();

    // logm = sum_j g_j u_j u_j^T  (coalesced transposed stores; symmetric).
    float* outm = g_logm + mat * (size_t)MATELEMS;
    for (int mi = 0; mi < 2; ++mi) {
        int m = t + mi * 32;
        for (int h = 0; h < 2; ++h) {
            float acc[32];
            #pragma unroll
            for (int n = 0; n < 32; ++n) acc[n] = 0.f;
            for (int j = 0; j < DIM; ++j) {
                float aj = gcoef[j] * U[j * LDU + m];
                const float* uj = &U[j * LDU + h * 32];
                #pragma unroll
                for (int n = 0; n < 32; ++n) acc[n] = fmaf(aj, uj[n], acc[n]);
            }
            #pragma unroll
            for (int n = 0; n < 32; ++n)
                outm[(size_t)(h * 32 + n) * DIM + m] = acc[n];
        }
    }
}

// ---------------------------------------------------------------------------
// Stage 2: mean over N.
// ---------------------------------------------------------------------------
__global__ void mean_kernel()
{
    int idx = blockIdx.x * blockDim.x + threadIdx.x;
    if (idx >= BATCH * MATELEMS) return;
    const float* p = g_logm + idx;
    float s = 0.f;
    #pragma unroll 4
    for (int i = 0; i < NMATS; ++i)
        s += p[(size_t)i * (BATCH * MATELEMS)];
    g_mean[idx] = s * (1.f / NMATS);
}

// ---------------------------------------------------------------------------
// Stage 3: expm via scaling-and-squaring Taylor (E = mean/16, degree-8
// Horner, 4 squarings). One 256-thread block per batch entry.
// ---------------------------------------------------------------------------
__device__ __forceinline__ void mm_acc(float* __restrict__ acc,
                                       const float* __restrict__ A,
                                       const float* __restrict__ Bm,
                                       int m, int nb)
{
    #pragma unroll
    for (int n = 0; n < 16; ++n) acc[n] = 0.f;
    for (int j = 0; j < DIM; ++j) {
        float av = A[m * LDU + j];
        const float* brow = &Bm[j * LDU + nb];
        #pragma unroll
        for (int n = 0; n < 16; ++n) acc[n] = fmaf(av, brow[n], acc[n]);
    }
}

__global__ __launch_bounds__(256) void expm_kernel(float* __restrict__ out)
{
    __shared__ float E[DIM * LDU];
    __shared__ float P[DIM * LDU];
    const int b = blockIdx.x;
    const int tid = threadIdx.x;
    const int m  = tid >> 2;
    const int nb = (tid & 3) << 4;

    for (int idx = tid; idx < MATELEMS; idx += 256) {
        int r = idx >> 6, c = idx & 63;
        float e = g_mean[b * MATELEMS + idx] * (1.f / 16.f);
        E[r * LDU + c] = e;
        P[r * LDU + c] = e * 0.125f + (r == c ? 1.f : 0.f);
    }
    __syncthreads();

    for (int k = 7; k >= 1; --k) {
        float acc[16];
        mm_acc(acc, E, P, m, nb);
        __syncthreads();
        float inv = 1.f / (float)k;
        #pragma unroll
        for (int n = 0; n < 16; ++n)
            P[m * LDU + nb + n] = acc[n] * inv + ((m == nb + n) ? 1.f : 0.f);
        __syncthreads();
    }

    for (int sq = 0; sq < 4; ++sq) {
        float acc[16];
        mm_acc(acc, P, P, m, nb);
        __syncthreads();
        #pragma unroll
        for (int n = 0; n < 16; ++n)
            P[m * LDU + nb + n] = acc[n];
        __syncthreads();
    }

    for (int idx = tid; idx < MATELEMS; idx += 256) {
        int r = idx >> 6, c = idx & 63;
        out[(size_t)b * MATELEMS + idx] = P[r * LDU + c];
    }
}

// ---------------------------------------------------------------------------
extern "C" void kernel_launch(void* const* d_in, const int* in_sizes, int n_in,
                              void* d_out, int out_size)
{
    (void)in_sizes; (void)n_in; (void)out_size;
    const float* X = (const float*)d_in[0];
    float* out = (float*)d_out;

    jacobi_log_kernel<<<TOTAL, 32>>>(X);
    mean_kernel<<<(BATCH * MATELEMS + 255) / 256, 256>>>();
    expm_kernel<<<BATCH, 256>>>(out);
}

// round 6
// speedup vs baseline: 3.0923x; 1.0599x over previous
#include <cuda_runtime.h>
#include <math.h>

#define NMATS 200
#define BATCH 64
#define DIM 64
#define TOTAL (NMATS * BATCH)      // 12800
#define MATELEMS (DIM * DIM)       // 4096
#define LDU 65
#define NSWEEPS 8
#define FULLMASK 0xffffffffu

__device__ float g_logm[(size_t)TOTAL * MATELEMS];
__device__ float g_mean[BATCH * MATELEMS];

// ---------------------------------------------------------------------------
// Stage 1: register-resident one-sided Jacobi with a recursive-bisection
// all-pairs schedule. 1 warp per matrix; thread t owns two columns (a, b)
// plus traveling scalars (norm, deferred-cosine scale). Per cross round only
// the b column rotates within its lane group (1 shfl.idx, no selects).
// Jacobi rotations are role-symmetric, and the final reconstruction
// sum_j g_j u_j u_j^T is order-invariant, so arbitrary column permutation
// across levels/sweeps is harmless.
// ---------------------------------------------------------------------------
__global__ __launch_bounds__(32) void jacobi_log_kernel(const float* __restrict__ X)
{
    __shared__ float U[DIM * LDU];
    __shared__ float gcoef[DIM];
    const int t = threadIdx.x;
    const size_t mat = blockIdx.x;
    const float* Xm = X + mat * (size_t)MATELEMS;

    // Coalesced load (X symmetric: row c == column c).
    for (int idx = t; idx < MATELEMS; idx += 32) {
        int c = idx >> 6, r = idx & 63;
        U[c * LDU + r] = Xm[idx];
    }
    __syncwarp();

    float a[DIM], b[DIM];
    #pragma unroll
    for (int i = 0; i < DIM; ++i) a[i] = U[(2 * t) * LDU + i];
    #pragma unroll
    for (int i = 0; i < DIM; ++i) b[i] = U[(2 * t + 1) * LDU + i];

    // Initial column norms; traveling scales = 1.
    float na, nb;
    {
        float p0 = 0.f, p1 = 0.f, q0 = 0.f, q1 = 0.f;
        #pragma unroll
        for (int i = 0; i < DIM; i += 2) {
            p0 = fmaf(a[i], a[i], p0);     p1 = fmaf(a[i+1], a[i+1], p1);
            q0 = fmaf(b[i], b[i], q0);     q1 = fmaf(b[i+1], b[i+1], q1);
        }
        na = p0 + p1; nb = q0 + q1;
    }
    float sa = 1.f, sb = 1.f;

    for (int sweep = 0; sweep < NSWEEPS; ++sweep) {
        bool sweep_active = false;
        int g = 32;                      // lanes per group (2g columns/group)
        #pragma unroll
        for (int level = 0; level < 6; ++level) {
            const int gm1 = g - 1;
            const int rot_src = (t & ~gm1) | ((t + 1) & gm1);  // b ring-rotate

            for (int r = 0; r < g; ++r) {
                // Cross dot of stored (scaled) columns, 4 chains for ILP.
                float d0 = 0.f, d1 = 0.f, d2 = 0.f, d3 = 0.f;
                #pragma unroll
                for (int i = 0; i < DIM; i += 4) {
                    d0 = fmaf(a[i],     b[i],     d0);
                    d1 = fmaf(a[i + 1], b[i + 1], d1);
                    d2 = fmaf(a[i + 2], b[i + 2], d2);
                    d3 = fmaf(a[i + 3], b[i + 3], d3);
                }
                float s01 = (d0 + d1) + (d2 + d3);
                float a01 = s01 * sa * sb;                // true off-diagonal

                float thr = 1e-7f * sqrtf(na * nb);
                bool act = fabsf(a01) > thr;
                sweep_active |= __any_sync(FULLMASK, act);

                float t1 = 0.f, t2 = 0.f;
                if (act) {                 // guard: a01 ~ 0 would give inf tau
                    float tau = (na - nb) / (2.f * a01);
                    float tt  = -copysignf(1.f, tau) / (fabsf(tau) + sqrtf(1.f + tau * tau));
                    float c   = rsqrtf(1.f + tt * tt);
                    float rr  = __fdividef(sb, sa);
                    t1 = tt * rr;                         // applied to stored y
                    t2 = __fdividef(tt, rr);              // applied to stored x
                    na = fmaf(-tt, a01, na);              // a00' = a00 - t*a01
                    nb = fmaf( tt, a01, nb);              // a11' = a11 + t*a01
                    sa *= c; sb *= c;                     // deferred cosine
                }

                // Fused rotate + ring-rotate of b within the group.
                #pragma unroll
                for (int i = 0; i < DIM; ++i) {
                    float x = a[i], y = b[i];
                    float xn = fmaf(-t1, y, x);
                    float yn = fmaf( t2, x, y);
                    a[i] = xn;
                    b[i] = __shfl_sync(FULLMASK, yn, rot_src);
                }
                nb = __shfl_sync(FULLMASK, nb, rot_src);
                sb = __shfl_sync(FULLMASK, sb, rot_src);
            }

            // Redistribute: low half-lanes collect the a-set, high half the
            // b-set; each lane receives exactly one column.
            if (g > 1) {
                const int half = g >> 1;
                const bool low = (t & gm1) < half;
                const int partner = low ? (t + half) : (t - half);
                #pragma unroll
                for (int i = 0; i < DIM; ++i) {
                    float send = low ? b[i] : a[i];
                    float recv = __shfl_sync(FULLMASK, send, partner);
                    if (low) b[i] = recv; else a[i] = recv;
                }
                float sn = low ? nb : na;
                float rn = __shfl_sync(FULLMASK, sn, partner);
                if (low) nb = rn; else na = rn;
                float ss = low ? sb : sa;
                float rs = __shfl_sync(FULLMASK, ss, partner);
                if (low) sb = rs; else sa = rs;
            }
            g >>= 1;
        }

        // Renormalize stored columns once per sweep.
        #pragma unroll
        for (int i = 0; i < DIM; ++i) { a[i] *= sa; b[i] *= sb; }
        sa = 1.f; sb = 1.f;

        if (!sweep_active) break;
    }

    // Exact final norms -> spectral coefficients; stash columns in smem.
    #pragma unroll
    for (int i = 0; i < DIM; ++i) U[(2 * t) * LDU + i] = a[i];
    #pragma unroll
    for (int i = 0; i < DIM; ++i) U[(2 * t + 1) * LDU + i] = b[i];
    {
        float p0 = 0.f, p1 = 0.f, q0 = 0.f, q1 = 0.f;
        #pragma unroll
        for (int i = 0; i < DIM; i += 2) {
            p0 = fmaf(a[i], a[i], p0);     p1 = fmaf(a[i+1], a[i+1], p1);
            q0 = fmaf(b[i], b[i], q0);     q1 = fmaf(b[i+1], b[i+1], q1);
        }
        float nna = p0 + p1, nnb = q0 + q1;        // lambda^2
        gcoef[2 * t]     = 0.5f * logf(nna) / nna;
        gcoef[2 * t + 1] = 0.5f * logf(nnb) / nnb;
    }
    __syncwarp();

    // logm = sum_j g_j u_j u_j^T  (order-invariant; coalesced stores).
    float* outm = g_logm + mat * (size_t)MATELEMS;
    for (int mi = 0; mi < 2; ++mi) {
        int m = t + mi * 32;
        for (int h = 0; h < 2; ++h) {
            float acc[32];
            #pragma unroll
            for (int n = 0; n < 32; ++n) acc[n] = 0.f;
            for (int j = 0; j < DIM; ++j) {
                float aj = gcoef[j] * U[j * LDU + m];
                const float* uj = &U[j * LDU + h * 32];
                #pragma unroll
                for (int n = 0; n < 32; ++n) acc[n] = fmaf(aj, uj[n], acc[n]);
            }
            #pragma unroll
            for (int n = 0; n < 32; ++n)
                outm[(size_t)(h * 32 + n) * DIM + m] = acc[n];
        }
    }
}

// ---------------------------------------------------------------------------
// Stage 2: mean over N.
// ---------------------------------------------------------------------------
__global__ void mean_kernel()
{
    int idx = blockIdx.x * blockDim.x + threadIdx.x;
    if (idx >= BATCH * MATELEMS) return;
    const float* p = g_logm + idx;
    float s = 0.f;
    #pragma unroll 4
    for (int i = 0; i < NMATS; ++i)
        s += p[(size_t)i * (BATCH * MATELEMS)];
    g_mean[idx] = s * (1.f / NMATS);
}

// ---------------------------------------------------------------------------
// Stage 3: expm via scaling-and-squaring Taylor (E = mean/16, degree-8
// Horner, 4 squarings). One 256-thread block per batch entry.
// ---------------------------------------------------------------------------
__device__ __forceinline__ void mm_acc(float* __restrict__ acc,
                                       const float* __restrict__ A,
                                       const float* __restrict__ Bm,
                                       int m, int nb)
{
    #pragma unroll
    for (int n = 0; n < 16; ++n) acc[n] = 0.f;
    for (int j = 0; j < DIM; ++j) {
        float av = A[m * LDU + j];
        const float* brow = &Bm[j * LDU + nb];
        #pragma unroll
        for (int n = 0; n < 16; ++n) acc[n] = fmaf(av, brow[n], acc[n]);
    }
}

__global__ __launch_bounds__(256) void expm_kernel(float* __restrict__ out)
{
    __shared__ float E[DIM * LDU];
    __shared__ float P[DIM * LDU];
    const int b = blockIdx.x;
    const int tid = threadIdx.x;
    const int m  = tid >> 2;
    const int nb = (tid & 3) << 4;

    for (int idx = tid; idx < MATELEMS; idx += 256) {
        int r = idx >> 6, c = idx & 63;
        float e = g_mean[b * MATELEMS + idx] * (1.f / 16.f);
        E[r * LDU + c] = e;
        P[r * LDU + c] = e * 0.125f + (r == c ? 1.f : 0.f);
    }
    __syncthreads();

    for (int k = 7; k >= 1; --k) {
        float acc[16];
        mm_acc(acc, E, P, m, nb);
        __syncthreads();
        float inv = 1.f / (float)k;
        #pragma unroll
        for (int n = 0; n < 16; ++n)
            P[m * LDU + nb + n] = acc[n] * inv + ((m == nb + n) ? 1.f : 0.f);
        __syncthreads();
    }

    for (int sq = 0; sq < 4; ++sq) {
        float acc[16];
        mm_acc(acc, P, P, m, nb);
        __syncthreads();
        #pragma unroll
        for (int n = 0; n < 16; ++n)
            P[m * LDU + nb + n] = acc[n];
        __syncthreads();
    }

    for (int idx = tid; idx < MATELEMS; idx += 256) {
        int r = idx >> 6, c = idx & 63;
        out[(size_t)b * MATELEMS + idx] = P[r * LDU + c];
    }
}

// ---------------------------------------------------------------------------
extern "C" void kernel_launch(void* const* d_in, const int* in_sizes, int n_in,
                              void* d_out, int out_size)
{
    (void)in_sizes; (void)n_in; (void)out_size;
    const float* X = (const float*)d_in[0];
    float* out = (float*)d_out;

    jacobi_log_kernel<<<TOTAL, 32>>>(X);
    mean_kernel<<<(BATCH * MATELEMS + 255) / 256, 256>>>();
    expm_kernel<<<BATCH, 256>>>(out);
}